// round 11
// baseline (speedup 1.0000x reference)
#include <cuda_runtime.h>
#include <cuda_bf16.h>
#include <cuda_fp16.h>
#include <cstdint>

#define BB 4
#define CH 64
#define NN 4096

// ---------------- scratch (allocation-free) ----------------
__device__ __align__(16) __nv_bfloat16 g_qhi[BB * NN * CH];
__device__ __align__(16) __nv_bfloat16 g_qlo[BB * NN * CH];
__device__ __align__(16) __nv_bfloat16 g_khi[BB * NN * CH];
__device__ __align__(16) __nv_bfloat16 g_klo[BB * NN * CH];
__device__ __align__(16) __half        g_vh [BB * CH * NN];

// ---------------- helpers (base-target PTX only) ----------------
__device__ __forceinline__ uint32_t smem_u32(const void* p) {
    uint32_t a;
    asm("{ .reg .u64 t; cvta.to.shared.u64 t, %1; cvt.u32.u64 %0, t; }"
        : "=r"(a) : "l"(p));
    return a;
}
__device__ __forceinline__ void cp16(uint32_t dst, const void* src) {
    asm volatile("cp.async.cg.shared.global [%0], [%1], 16;"
                 :: "r"(dst), "l"(__cvta_generic_to_global(src)) : "memory");
}
__device__ __forceinline__ void cp_commit() {
    asm volatile("cp.async.commit_group;" ::: "memory");
}
__device__ __forceinline__ void cp_wait1() {
    asm volatile("cp.async.wait_group 1;" ::: "memory");
}
__device__ __forceinline__ void cp_wait0() {
    asm volatile("cp.async.wait_group 0;" ::: "memory");
}
__device__ __forceinline__ void ldsm4(uint32_t& r0, uint32_t& r1, uint32_t& r2,
                                      uint32_t& r3, uint32_t a) {
    asm volatile("ldmatrix.sync.aligned.m8n8.x4.shared.b16 {%0,%1,%2,%3}, [%4];"
                 : "=r"(r0), "=r"(r1), "=r"(r2), "=r"(r3) : "r"(a));
}
__device__ __forceinline__ void mma_bf(float* d, const uint32_t* a,
                                       uint32_t b0, uint32_t b1) {
    asm volatile("mma.sync.aligned.m16n8k16.row.col.f32.bf16.bf16.f32 "
                 "{%0,%1,%2,%3}, {%4,%5,%6,%7}, {%8,%9}, {%0,%1,%2,%3};"
                 : "+f"(d[0]), "+f"(d[1]), "+f"(d[2]), "+f"(d[3])
                 : "r"(a[0]), "r"(a[1]), "r"(a[2]), "r"(a[3]), "r"(b0), "r"(b1));
}
__device__ __forceinline__ void mma_fp(float* d, const uint32_t* a,
                                       uint32_t b0, uint32_t b1) {
    asm volatile("mma.sync.aligned.m16n8k16.row.col.f32.f16.f16.f32 "
                 "{%0,%1,%2,%3}, {%4,%5,%6,%7}, {%8,%9}, {%0,%1,%2,%3};"
                 : "+f"(d[0]), "+f"(d[1]), "+f"(d[2]), "+f"(d[3])
                 : "r"(a[0]), "r"(a[1]), "r"(a[2]), "r"(a[3]), "r"(b0), "r"(b1));
}
__device__ __forceinline__ uint32_t b2u(__nv_bfloat162 h) {
    return *reinterpret_cast<uint32_t*>(&h);
}
__device__ __forceinline__ uint32_t h2u(__half2 h) {
    return *reinterpret_cast<uint32_t*>(&h);
}
__device__ __forceinline__ float ex2a(float x) {
    float r;
    asm("ex2.approx.f32 %0, %1;" : "=f"(r) : "f"(x));
    return r;
}
#define L2E 1.44269504f

// ---------------------------------------------------------------------------
// Stage 1: projections. Q/K: bf16 hi/lo [B][N][C]; V: fp16 [B][C][N].
// ---------------------------------------------------------------------------
#define QKV_SMEM 69632

__global__ __launch_bounds__(256) void qkv_kernel(
    const float* __restrict__ x,
    const float* __restrict__ Wq, const float* __restrict__ bq,
    const float* __restrict__ Wk, const float* __restrict__ bk,
    const float* __restrict__ Wv, const float* __restrict__ bv,
    const float* __restrict__ rel_h, const float* __restrict__ rel_w)
{
    extern __shared__ float sm1[];
    float* w_s = sm1;              // [3][64 c][68]
    float* xs  = sm1 + 13056;      // [64 c][68]
    float* res = xs;               // alias

    int b  = blockIdx.x >> 6;
    int n0 = (blockIdx.x & 63) << 6;
    int t  = threadIdx.x;

    for (int i = t; i < 4096; i += 256) {
        int o = i >> 6, c = i & 63;
        w_s[c * 68 + o]        = Wq[i];
        w_s[4352 + c * 68 + o] = Wk[i];
        w_s[8704 + c * 68 + o] = Wv[i];
        xs[o * 68 + c]         = x[((long)b * CH + o) * NN + n0 + c];
    }
    __syncthreads();

    int og = (t & 15) << 2;
    int ng = (t >> 4) << 2;

    float aq[4][4] = {}, ak[4][4] = {}, av[4][4] = {};
    #pragma unroll 4
    for (int c = 0; c < 64; c++) {
        float4 xv4 = *(const float4*)&xs[c * 68 + ng];
        float4 wq4 = *(const float4*)&w_s[c * 68 + og];
        float4 wk4 = *(const float4*)&w_s[4352 + c * 68 + og];
        float4 wv4 = *(const float4*)&w_s[8704 + c * 68 + og];
        float xv[4] = {xv4.x, xv4.y, xv4.z, xv4.w};
        float wq[4] = {wq4.x, wq4.y, wq4.z, wq4.w};
        float wk[4] = {wk4.x, wk4.y, wk4.z, wk4.w};
        float wv[4] = {wv4.x, wv4.y, wv4.z, wv4.w};
        #pragma unroll
        for (int i = 0; i < 4; i++)
            #pragma unroll
            for (int j = 0; j < 4; j++) {
                aq[i][j] = fmaf(wq[i], xv[j], aq[i][j]);
                ak[i][j] = fmaf(wk[i], xv[j], ak[i][j]);
                av[i][j] = fmaf(wv[i], xv[j], av[i][j]);
            }
    }

    long nbase = ((long)b * NN + n0) * CH;
    float bq0 = __ldg(&bq[og]), bq1 = __ldg(&bq[og + 1]),
          bq2 = __ldg(&bq[og + 2]), bq3 = __ldg(&bq[og + 3]);
    float bk0 = __ldg(&bk[og]), bk1 = __ldg(&bk[og + 1]),
          bk2 = __ldg(&bk[og + 2]), bk3 = __ldg(&bk[og + 3]);

    #pragma unroll
    for (int j = 0; j < 4; j++) {
        int gn = n0 + ng + j, hh = gn >> 6, ww = gn & 63;
        long row = nbase + (long)(ng + j) * CH + og;
        {
            float v0 = aq[0][j] + bq0, v1 = aq[1][j] + bq1;
            float v2 = aq[2][j] + bq2, v3 = aq[3][j] + bq3;
            __nv_bfloat162 h01 = __floats2bfloat162_rn(v0, v1);
            __nv_bfloat162 h23 = __floats2bfloat162_rn(v2, v3);
            __nv_bfloat162 l01 = __floats2bfloat162_rn(v0 - __bfloat162float(h01.x),
                                                       v1 - __bfloat162float(h01.y));
            __nv_bfloat162 l23 = __floats2bfloat162_rn(v2 - __bfloat162float(h23.x),
                                                       v3 - __bfloat162float(h23.y));
            *(uint2*)&g_qhi[row] = make_uint2(b2u(h01), b2u(h23));
            *(uint2*)&g_qlo[row] = make_uint2(b2u(l01), b2u(l23));
        }
        {
            float v0 = ak[0][j] + bk0 + __ldg(&rel_h[og * 64 + hh])       + __ldg(&rel_w[og * 64 + ww]);
            float v1 = ak[1][j] + bk1 + __ldg(&rel_h[(og + 1) * 64 + hh]) + __ldg(&rel_w[(og + 1) * 64 + ww]);
            float v2 = ak[2][j] + bk2 + __ldg(&rel_h[(og + 2) * 64 + hh]) + __ldg(&rel_w[(og + 2) * 64 + ww]);
            float v3 = ak[3][j] + bk3 + __ldg(&rel_h[(og + 3) * 64 + hh]) + __ldg(&rel_w[(og + 3) * 64 + ww]);
            __nv_bfloat162 h01 = __floats2bfloat162_rn(v0, v1);
            __nv_bfloat162 h23 = __floats2bfloat162_rn(v2, v3);
            __nv_bfloat162 l01 = __floats2bfloat162_rn(v0 - __bfloat162float(h01.x),
                                                       v1 - __bfloat162float(h01.y));
            __nv_bfloat162 l23 = __floats2bfloat162_rn(v2 - __bfloat162float(h23.x),
                                                       v3 - __bfloat162float(h23.y));
            *(uint2*)&g_khi[row] = make_uint2(b2u(h01), b2u(h23));
            *(uint2*)&g_klo[row] = make_uint2(b2u(l01), b2u(l23));
        }
    }

    __syncthreads();
    float bv0 = __ldg(&bv[og]), bv1 = __ldg(&bv[og + 1]),
          bv2 = __ldg(&bv[og + 2]), bv3 = __ldg(&bv[og + 3]);
    #pragma unroll
    for (int j = 0; j < 4; j++) {
        res[(og + 0) * 65 + ng + j] = av[0][j] + bv0;
        res[(og + 1) * 65 + ng + j] = av[1][j] + bv1;
        res[(og + 2) * 65 + ng + j] = av[2][j] + bv2;
        res[(og + 3) * 65 + ng + j] = av[3][j] + bv3;
    }
    __syncthreads();
    for (int i = t; i < 2048; i += 256) {
        int e = i * 2, c = e >> 6, n = e & 63;
        __half2 h = __floats2half2_rn(res[c * 65 + n], res[c * 65 + n + 1]);
        *(__half2*)&g_vh[((long)b * CH + c) * NN + n0 + n] = h;
    }
}

// ---------------------------------------------------------------------------
// Stage 2: FA2 with true online softmax (chunk-level row max, O rescale).
// QK: bf16 hi/lo 3-pass. PV: fp16 single-pass (p in (0,1] — no overflow).
// 256 threads, 128 q-rows, 128-key KV tiles double-buffered.
// smem: QHI 16K | QLO 16K | buf0 48K | buf1 48K  (buffer: KHI|KLO 16K, V 16K)
// ---------------------------------------------------------------------------
#define SM_KV    32768
#define KV_BYTES 49152
#define ATT_SMEM (32768 + 2 * 49152)   // 131072

__device__ __forceinline__ void load_kv(uint32_t base, int b, int m0, int tid) {
    const __nv_bfloat16* kh = g_khi + ((long)b * NN + m0) * CH;
    const __nv_bfloat16* kl = g_klo + ((long)b * NN + m0) * CH;
    #pragma unroll
    for (int j = 0; j < 4; j++) {
        int i = tid + j * 256;
        int m = i >> 3, ch = i & 7;
        uint32_t d = base + (m << 7) + (((ch ^ (m & 7)) & 7) << 4);
        cp16(d, kh + m * 64 + ch * 8);
        cp16(d + 16384, kl + m * 64 + ch * 8);
    }
    const __half* vh = g_vh + (long)b * CH * NN + m0;
    #pragma unroll
    for (int j = 0; j < 4; j++) {
        int i = tid + j * 256;
        int c = i >> 4, ch = i & 15;
        uint32_t d = base + 32768 + (c << 8)
                   + ((((ch & 8) | ((ch ^ (c & 7)) & 7))) << 4);
        cp16(d, vh + (long)c * NN + ch * 8);
    }
}

__global__ __launch_bounds__(256, 1) void attn_kernel(float* __restrict__ out)
{
    extern __shared__ char smem[];
    uint32_t sb = smem_u32(smem);
    int tid = threadIdx.x;
    int w = tid >> 5, lane = tid & 31;
    int b  = blockIdx.x >> 5;
    int n0 = (blockIdx.x & 31) << 7;

    // ---- prologue: Q tile group, then KV tile 0 group ----
    {
        const __nv_bfloat16* qh = g_qhi + ((long)b * NN + n0) * CH;
        const __nv_bfloat16* ql = g_qlo + ((long)b * NN + n0) * CH;
        #pragma unroll
        for (int j = 0; j < 4; j++) {
            int i = tid + j * 256;
            int m = i >> 3, ch = i & 7;
            uint32_t d = sb + (m << 7) + (((ch ^ (m & 7)) & 7) << 4);
            cp16(d, qh + m * 64 + ch * 8);
            cp16(d + 16384, ql + m * 64 + ch * 8);
        }
        cp_commit();
    }
    load_kv(sb + SM_KV, b, 0, tid);
    cp_commit();
    cp_wait1();           // Q group done
    __syncthreads();

    int r15 = lane & 15, c16 = lane >> 4;
    int r7 = r15 & 7;

    // ---- Q fragments, register-resident for the whole loop ----
    uint32_t qfh[4][4], qfl[4][4];
    #pragma unroll
    for (int kk = 0; kk < 4; kk++) {
        int r = w * 16 + r15;
        int cc = kk * 2 + c16;
        uint32_t a = sb + (r << 7) + (((cc ^ (r & 7)) & 7) << 4);
        ldsm4(qfh[kk][0], qfh[kk][1], qfh[kk][2], qfh[kk][3], a);
        ldsm4(qfl[kk][0], qfl[kk][1], qfl[kk][2], qfl[kk][3], a + 16384);
    }

    float O[8][4];
    #pragma unroll
    for (int i = 0; i < 8; i++)
        #pragma unroll
        for (int j = 0; j < 4; j++) O[i][j] = 0.f;
    float la = 0.f, lb = 0.f;          // per-lane partial row sums
    float ma = -1e30f, mb = -1e30f;    // running row maxes (rows ra, rb)

    for (int it = 0; it < 32; it++) {
        cp_wait0();
        __syncthreads();
        if (it + 1 < 32) {
            load_kv(sb + SM_KV + ((it + 1) & 1) * KV_BYTES, b, (it + 1) << 7, tid);
            cp_commit();
        }
        uint32_t kv  = sb + SM_KV + (it & 1) * KV_BYTES;
        uint32_t vhB = kv + 32768;

        uint32_t kbase[4];
        #pragma unroll
        for (int kk = 0; kk < 4; kk++)
            kbase[kk] = kv + (r15 << 7) + ((((kk * 2 + c16) ^ r7) & 7) << 4);

        #pragma unroll
        for (int p = 0; p < 8; p++) {
            // ---- K fragments for this 16-key chunk ----
            uint32_t bh[4][4], bl[4][4];
            #pragma unroll
            for (int kk = 0; kk < 4; kk++) {
                uint32_t a = kbase[kk] + (p << 11);
                ldsm4(bh[kk][0], bh[kk][1], bh[kk][2], bh[kk][3], a);
                ldsm4(bl[kk][0], bl[kk][1], bl[kk][2], bl[kk][3], a + 16384);
            }
            // ---- MMA1: S = Qhi Khi + Qhi Klo + Qlo Khi (bf16, 3-pass) ----
            float S0[4] = {0.f, 0.f, 0.f, 0.f};
            float S1[4] = {0.f, 0.f, 0.f, 0.f};
            #pragma unroll
            for (int kk = 0; kk < 4; kk++) {
                mma_bf(S0, qfh[kk], bh[kk][0], bh[kk][2]);
                mma_bf(S1, qfh[kk], bh[kk][1], bh[kk][3]);
                mma_bf(S0, qfh[kk], bl[kk][0], bl[kk][2]);
                mma_bf(S1, qfh[kk], bl[kk][1], bl[kk][3]);
                mma_bf(S0, qfl[kk], bh[kk][0], bh[kk][2]);
                mma_bf(S1, qfl[kk], bh[kk][1], bh[kk][3]);
            }
            // ---- online softmax: chunk row max, rescale, p in (0,1] ----
            float ca = fmaxf(fmaxf(S0[0], S0[1]), fmaxf(S1[0], S1[1]));
            float cb = fmaxf(fmaxf(S0[2], S0[3]), fmaxf(S1[2], S1[3]));
            ca = fmaxf(ca, __shfl_xor_sync(0xffffffffu, ca, 1));
            ca = fmaxf(ca, __shfl_xor_sync(0xffffffffu, ca, 2));
            cb = fmaxf(cb, __shfl_xor_sync(0xffffffffu, cb, 1));
            cb = fmaxf(cb, __shfl_xor_sync(0xffffffffu, cb, 2));
            float mna = fmaxf(ma, ca), mnb = fmaxf(mb, cb);
            float fa = mna * L2E, fb = mnb * L2E;
            float sa = ex2a(ma * L2E - fa);     // exp(ma - mna), 1.0 when no change
            float sbb = ex2a(mb * L2E - fb);
            ma = mna; mb = mnb;

            float e00 = ex2a(fmaf(S0[0], L2E, -fa));
            float e01 = ex2a(fmaf(S0[1], L2E, -fa));
            float e02 = ex2a(fmaf(S0[2], L2E, -fb));
            float e03 = ex2a(fmaf(S0[3], L2E, -fb));
            float e10 = ex2a(fmaf(S1[0], L2E, -fa));
            float e11 = ex2a(fmaf(S1[1], L2E, -fa));
            float e12 = ex2a(fmaf(S1[2], L2E, -fb));
            float e13 = ex2a(fmaf(S1[3], L2E, -fb));
            la = la * sa  + e00 + e01 + e10 + e11;
            lb = lb * sbb + e02 + e03 + e12 + e13;
            #pragma unroll
            for (int nb = 0; nb < 8; nb++) {
                O[nb][0] *= sa;  O[nb][1] *= sa;
                O[nb][2] *= sbb; O[nb][3] *= sbb;
            }
            uint32_t Ah[4] = {h2u(__floats2half2_rn(e00, e01)),
                              h2u(__floats2half2_rn(e02, e03)),
                              h2u(__floats2half2_rn(e10, e11)),
                              h2u(__floats2half2_rn(e12, e13))};

            // ---- MMA2: O += P Vh (fp16, single pass) ----
            uint32_t vb = vhB + (r15 << 8)
                        + ((((p * 2 + c16) & 8) | (((p * 2 + c16) ^ r7) & 7)) << 4);
            #pragma unroll
            for (int np = 0; np < 4; np++) {
                uint32_t a = vb + (np << 12);
                uint32_t v0, v1, v2, v3;
                ldsm4(v0, v1, v2, v3, a);
                mma_fp(O[2 * np],     Ah, v0, v2);
                mma_fp(O[2 * np + 1], Ah, v1, v3);
            }
        }
    }

    // ---- epilogue: per-row l (quad reduce), normalize, coalesced store ----
    la += __shfl_xor_sync(0xffffffffu, la, 1);
    la += __shfl_xor_sync(0xffffffffu, la, 2);
    lb += __shfl_xor_sync(0xffffffffu, lb, 1);
    lb += __shfl_xor_sync(0xffffffffu, lb, 2);
    float ia = 1.0f / la, ib = 1.0f / lb;

    __syncthreads();
    float* o_s = (float*)smem;          // [64][132], overlays Q/KV smem
    #pragma unroll
    for (int nb = 0; nb < 8; nb++) {
        int c = nb * 8 + (lane & 3) * 2;
        int m = w * 16 + (lane >> 2);
        o_s[c * 132 + m]           = O[nb][0] * ia;
        o_s[(c + 1) * 132 + m]     = O[nb][1] * ia;
        o_s[c * 132 + m + 8]       = O[nb][2] * ib;
        o_s[(c + 1) * 132 + m + 8] = O[nb][3] * ib;
    }
    __syncthreads();
    for (int i = tid; i < 2048; i += 256) {
        int c = i >> 5, sg = i & 31;
        float4 v;
        v.x = o_s[c * 132 + sg * 4 + 0];
        v.y = o_s[c * 132 + sg * 4 + 1];
        v.z = o_s[c * 132 + sg * 4 + 2];
        v.w = o_s[c * 132 + sg * 4 + 3];
        *(float4*)(out + ((long)(b * CH + c)) * NN + n0 + sg * 4) = v;
    }
}

extern "C" void kernel_launch(void* const* d_in, const int* in_sizes, int n_in,
                              void* d_out, int out_size)
{
    const float* x     = (const float*)d_in[0];
    const float* Wq    = (const float*)d_in[1];
    const float* bq    = (const float*)d_in[2];
    const float* Wk    = (const float*)d_in[3];
    const float* bk    = (const float*)d_in[4];
    const float* Wv    = (const float*)d_in[5];
    const float* bv    = (const float*)d_in[6];
    const float* rel_h = (const float*)d_in[7];
    const float* rel_w = (const float*)d_in[8];
    float* out = (float*)d_out;

    cudaFuncSetAttribute(qkv_kernel, cudaFuncAttributeMaxDynamicSharedMemorySize,
                         QKV_SMEM);
    cudaFuncSetAttribute(attn_kernel, cudaFuncAttributeMaxDynamicSharedMemorySize,
                         ATT_SMEM);

    qkv_kernel<<<BB * 64, 256, QKV_SMEM>>>(x, Wq, bq, Wk, bk, Wv, bv, rel_h, rel_w);
    attn_kernel<<<BB * 32, 256, ATT_SMEM>>>(out);
}

// round 12
// speedup vs baseline: 1.5302x; 1.5302x over previous
#include <cuda_runtime.h>
#include <cuda_bf16.h>
#include <cuda_fp16.h>
#include <cstdint>

#define BB 4
#define CH 64
#define NN 4096

// ---------------- scratch (allocation-free) ----------------
__device__ __align__(16) __nv_bfloat16 g_qhi[BB * NN * CH];
__device__ __align__(16) __nv_bfloat16 g_qlo[BB * NN * CH];
__device__ __align__(16) __nv_bfloat16 g_khi[BB * NN * CH];
__device__ __align__(16) __nv_bfloat16 g_klo[BB * NN * CH];
__device__ __align__(16) __half        g_vh [BB * CH * NN];

// ---------------- helpers (base-target PTX only) ----------------
__device__ __forceinline__ uint32_t smem_u32(const void* p) {
    uint32_t a;
    asm("{ .reg .u64 t; cvta.to.shared.u64 t, %1; cvt.u32.u64 %0, t; }"
        : "=r"(a) : "l"(p));
    return a;
}
__device__ __forceinline__ void cp16(uint32_t dst, const void* src) {
    asm volatile("cp.async.cg.shared.global [%0], [%1], 16;"
                 :: "r"(dst), "l"(__cvta_generic_to_global(src)) : "memory");
}
__device__ __forceinline__ void cp_commit() {
    asm volatile("cp.async.commit_group;" ::: "memory");
}
__device__ __forceinline__ void cp_wait1() {
    asm volatile("cp.async.wait_group 1;" ::: "memory");
}
__device__ __forceinline__ void cp_wait0() {
    asm volatile("cp.async.wait_group 0;" ::: "memory");
}
__device__ __forceinline__ void ldsm4(uint32_t& r0, uint32_t& r1, uint32_t& r2,
                                      uint32_t& r3, uint32_t a) {
    asm volatile("ldmatrix.sync.aligned.m8n8.x4.shared.b16 {%0,%1,%2,%3}, [%4];"
                 : "=r"(r0), "=r"(r1), "=r"(r2), "=r"(r3) : "r"(a));
}
__device__ __forceinline__ void mma_bf(float* d, const uint32_t* a,
                                       uint32_t b0, uint32_t b1) {
    asm volatile("mma.sync.aligned.m16n8k16.row.col.f32.bf16.bf16.f32 "
                 "{%0,%1,%2,%3}, {%4,%5,%6,%7}, {%8,%9}, {%0,%1,%2,%3};"
                 : "+f"(d[0]), "+f"(d[1]), "+f"(d[2]), "+f"(d[3])
                 : "r"(a[0]), "r"(a[1]), "r"(a[2]), "r"(a[3]), "r"(b0), "r"(b1));
}
__device__ __forceinline__ void mma_fp(float* d, const uint32_t* a,
                                       uint32_t b0, uint32_t b1) {
    asm volatile("mma.sync.aligned.m16n8k16.row.col.f32.f16.f16.f32 "
                 "{%0,%1,%2,%3}, {%4,%5,%6,%7}, {%8,%9}, {%0,%1,%2,%3};"
                 : "+f"(d[0]), "+f"(d[1]), "+f"(d[2]), "+f"(d[3])
                 : "r"(a[0]), "r"(a[1]), "r"(a[2]), "r"(a[3]), "r"(b0), "r"(b1));
}
__device__ __forceinline__ uint32_t b2u(__nv_bfloat162 h) {
    return *reinterpret_cast<uint32_t*>(&h);
}
__device__ __forceinline__ uint32_t h2u(__half2 h) {
    return *reinterpret_cast<uint32_t*>(&h);
}
__device__ __forceinline__ float ex2a(float x) {
    float r;
    asm("ex2.approx.f32 %0, %1;" : "=f"(r) : "f"(x));
    return r;
}
#define L2E 1.44269504f

// ---------------------------------------------------------------------------
// Stage 1: projections. Q/K: bf16 hi/lo [B][N][C]; V: fp16 [B][C][N].
// ---------------------------------------------------------------------------
#define QKV_SMEM 69632

__global__ __launch_bounds__(256) void qkv_kernel(
    const float* __restrict__ x,
    const float* __restrict__ Wq, const float* __restrict__ bq,
    const float* __restrict__ Wk, const float* __restrict__ bk,
    const float* __restrict__ Wv, const float* __restrict__ bv,
    const float* __restrict__ rel_h, const float* __restrict__ rel_w)
{
    extern __shared__ float sm1[];
    float* w_s = sm1;              // [3][64 c][68]
    float* xs  = sm1 + 13056;      // [64 c][68]
    float* res = xs;               // alias

    int b  = blockIdx.x >> 6;
    int n0 = (blockIdx.x & 63) << 6;
    int t  = threadIdx.x;

    for (int i = t; i < 4096; i += 256) {
        int o = i >> 6, c = i & 63;
        w_s[c * 68 + o]        = Wq[i];
        w_s[4352 + c * 68 + o] = Wk[i];
        w_s[8704 + c * 68 + o] = Wv[i];
        xs[o * 68 + c]         = x[((long)b * CH + o) * NN + n0 + c];
    }
    __syncthreads();

    int og = (t & 15) << 2;
    int ng = (t >> 4) << 2;

    float aq[4][4] = {}, ak[4][4] = {}, av[4][4] = {};
    #pragma unroll 4
    for (int c = 0; c < 64; c++) {
        float4 xv4 = *(const float4*)&xs[c * 68 + ng];
        float4 wq4 = *(const float4*)&w_s[c * 68 + og];
        float4 wk4 = *(const float4*)&w_s[4352 + c * 68 + og];
        float4 wv4 = *(const float4*)&w_s[8704 + c * 68 + og];
        float xv[4] = {xv4.x, xv4.y, xv4.z, xv4.w};
        float wq[4] = {wq4.x, wq4.y, wq4.z, wq4.w};
        float wk[4] = {wk4.x, wk4.y, wk4.z, wk4.w};
        float wv[4] = {wv4.x, wv4.y, wv4.z, wv4.w};
        #pragma unroll
        for (int i = 0; i < 4; i++)
            #pragma unroll
            for (int j = 0; j < 4; j++) {
                aq[i][j] = fmaf(wq[i], xv[j], aq[i][j]);
                ak[i][j] = fmaf(wk[i], xv[j], ak[i][j]);
                av[i][j] = fmaf(wv[i], xv[j], av[i][j]);
            }
    }

    long nbase = ((long)b * NN + n0) * CH;
    float bq0 = __ldg(&bq[og]), bq1 = __ldg(&bq[og + 1]),
          bq2 = __ldg(&bq[og + 2]), bq3 = __ldg(&bq[og + 3]);
    float bk0 = __ldg(&bk[og]), bk1 = __ldg(&bk[og + 1]),
          bk2 = __ldg(&bk[og + 2]), bk3 = __ldg(&bk[og + 3]);

    #pragma unroll
    for (int j = 0; j < 4; j++) {
        int gn = n0 + ng + j, hh = gn >> 6, ww = gn & 63;
        long row = nbase + (long)(ng + j) * CH + og;
        {
            float v0 = aq[0][j] + bq0, v1 = aq[1][j] + bq1;
            float v2 = aq[2][j] + bq2, v3 = aq[3][j] + bq3;
            __nv_bfloat162 h01 = __floats2bfloat162_rn(v0, v1);
            __nv_bfloat162 h23 = __floats2bfloat162_rn(v2, v3);
            __nv_bfloat162 l01 = __floats2bfloat162_rn(v0 - __bfloat162float(h01.x),
                                                       v1 - __bfloat162float(h01.y));
            __nv_bfloat162 l23 = __floats2bfloat162_rn(v2 - __bfloat162float(h23.x),
                                                       v3 - __bfloat162float(h23.y));
            *(uint2*)&g_qhi[row] = make_uint2(b2u(h01), b2u(h23));
            *(uint2*)&g_qlo[row] = make_uint2(b2u(l01), b2u(l23));
        }
        {
            float v0 = ak[0][j] + bk0 + __ldg(&rel_h[og * 64 + hh])       + __ldg(&rel_w[og * 64 + ww]);
            float v1 = ak[1][j] + bk1 + __ldg(&rel_h[(og + 1) * 64 + hh]) + __ldg(&rel_w[(og + 1) * 64 + ww]);
            float v2 = ak[2][j] + bk2 + __ldg(&rel_h[(og + 2) * 64 + hh]) + __ldg(&rel_w[(og + 2) * 64 + ww]);
            float v3 = ak[3][j] + bk3 + __ldg(&rel_h[(og + 3) * 64 + hh]) + __ldg(&rel_w[(og + 3) * 64 + ww]);
            __nv_bfloat162 h01 = __floats2bfloat162_rn(v0, v1);
            __nv_bfloat162 h23 = __floats2bfloat162_rn(v2, v3);
            __nv_bfloat162 l01 = __floats2bfloat162_rn(v0 - __bfloat162float(h01.x),
                                                       v1 - __bfloat162float(h01.y));
            __nv_bfloat162 l23 = __floats2bfloat162_rn(v2 - __bfloat162float(h23.x),
                                                       v3 - __bfloat162float(h23.y));
            *(uint2*)&g_khi[row] = make_uint2(b2u(h01), b2u(h23));
            *(uint2*)&g_klo[row] = make_uint2(b2u(l01), b2u(l23));
        }
    }

    __syncthreads();
    float bv0 = __ldg(&bv[og]), bv1 = __ldg(&bv[og + 1]),
          bv2 = __ldg(&bv[og + 2]), bv3 = __ldg(&bv[og + 3]);
    #pragma unroll
    for (int j = 0; j < 4; j++) {
        res[(og + 0) * 65 + ng + j] = av[0][j] + bv0;
        res[(og + 1) * 65 + ng + j] = av[1][j] + bv1;
        res[(og + 2) * 65 + ng + j] = av[2][j] + bv2;
        res[(og + 3) * 65 + ng + j] = av[3][j] + bv3;
    }
    __syncthreads();
    for (int i = t; i < 2048; i += 256) {
        int e = i * 2, c = e >> 6, n = e & 63;
        __half2 h = __floats2half2_rn(res[c * 65 + n], res[c * 65 + n + 1]);
        *(__half2*)&g_vh[((long)b * CH + c) * NN + n0 + n] = h;
    }
}

// ---------------------------------------------------------------------------
// Stage 2: FA2, online softmax at 64-key TILE granularity (one max/rescale
// per tile). QK: bf16 hi/lo 3-pass. PV: fp16 single-pass (p in (0,1]).
// 256 threads, 128 q-rows, 64-key KV tiles double-buffered.
// smem: QHI 16K | QLO 16K | buf0 24K | buf1 24K  (buffer: KHI 8K|KLO 8K|V 8K)
// ---------------------------------------------------------------------------
#define SM_KV    32768
#define KV_BYTES 24576
#define ATT_SMEM (32768 + 2 * 24576)   // 81920

__device__ __forceinline__ void load_kv(uint32_t base, int b, int m0, int tid) {
    const __nv_bfloat16* kh = g_khi + ((long)b * NN + m0) * CH;
    const __nv_bfloat16* kl = g_klo + ((long)b * NN + m0) * CH;
    #pragma unroll
    for (int j = 0; j < 2; j++) {
        int i = tid + j * 256;
        int m = i >> 3, ch = i & 7;
        uint32_t d = base + (m << 7) + (((ch ^ (m & 7)) & 7) << 4);
        cp16(d, kh + m * 64 + ch * 8);
        cp16(d + 8192, kl + m * 64 + ch * 8);
    }
    const __half* vh = g_vh + (long)b * CH * NN + m0;
    #pragma unroll
    for (int j = 0; j < 2; j++) {
        int i = tid + j * 256;
        int c = i >> 3, ch = i & 7;
        uint32_t d = base + 16384 + (c << 7) + (((ch ^ (c & 7)) & 7) << 4);
        cp16(d, vh + (long)c * NN + ch * 8);
    }
}

__global__ __launch_bounds__(256, 1) void attn_kernel(float* __restrict__ out)
{
    extern __shared__ char smem[];
    uint32_t sb = smem_u32(smem);
    int tid = threadIdx.x;
    int w = tid >> 5, lane = tid & 31;
    int b  = blockIdx.x >> 5;
    int n0 = (blockIdx.x & 31) << 7;

    // ---- prologue: Q tile group, then KV tile 0 group ----
    {
        const __nv_bfloat16* qh = g_qhi + ((long)b * NN + n0) * CH;
        const __nv_bfloat16* ql = g_qlo + ((long)b * NN + n0) * CH;
        #pragma unroll
        for (int j = 0; j < 4; j++) {
            int i = tid + j * 256;
            int m = i >> 3, ch = i & 7;
            uint32_t d = sb + (m << 7) + (((ch ^ (m & 7)) & 7) << 4);
            cp16(d, qh + m * 64 + ch * 8);
            cp16(d + 16384, ql + m * 64 + ch * 8);
        }
        cp_commit();
    }
    load_kv(sb + SM_KV, b, 0, tid);
    cp_commit();
    cp_wait1();           // Q group done
    __syncthreads();

    int r15 = lane & 15, c16 = lane >> 4;
    int r7 = r15 & 7;

    // ---- Q fragments, register-resident for the whole loop ----
    uint32_t qfh[4][4], qfl[4][4];
    #pragma unroll
    for (int kk = 0; kk < 4; kk++) {
        int r = w * 16 + r15;
        int cc = kk * 2 + c16;
        uint32_t a = sb + (r << 7) + (((cc ^ (r & 7)) & 7) << 4);
        ldsm4(qfh[kk][0], qfh[kk][1], qfh[kk][2], qfh[kk][3], a);
        ldsm4(qfl[kk][0], qfl[kk][1], qfl[kk][2], qfl[kk][3], a + 16384);
    }

    float O[8][4];
    #pragma unroll
    for (int i = 0; i < 8; i++)
        #pragma unroll
        for (int j = 0; j < 4; j++) O[i][j] = 0.f;
    float la = 0.f, lb = 0.f;
    float ma = -1e30f, mb = -1e30f;

    uint32_t ksw[4];
    #pragma unroll
    for (int kk = 0; kk < 4; kk++)
        ksw[kk] = (r15 << 7) + ((((kk * 2 + c16) ^ r7) & 7) << 4);

    for (int it = 0; it < 64; it++) {
        cp_wait0();
        __syncthreads();
        if (it + 1 < 64) {
            load_kv(sb + SM_KV + ((it + 1) & 1) * KV_BYTES, b, (it + 1) << 6, tid);
            cp_commit();
        }
        uint32_t kv  = sb + SM_KV + (it & 1) * KV_BYTES;
        uint32_t vhB = kv + 16384;

        // ---- MMA1 for all 4 chunks of this tile; S kept in registers ----
        float S0a[4][4], S1a[4][4];
        #pragma unroll
        for (int p = 0; p < 4; p++) {
            uint32_t bh[4][4], bl[4][4];
            #pragma unroll
            for (int kk = 0; kk < 4; kk++) {
                uint32_t a = kv + ksw[kk] + (p << 11);
                ldsm4(bh[kk][0], bh[kk][1], bh[kk][2], bh[kk][3], a);
                ldsm4(bl[kk][0], bl[kk][1], bl[kk][2], bl[kk][3], a + 8192);
            }
            #pragma unroll
            for (int j = 0; j < 4; j++) { S0a[p][j] = 0.f; S1a[p][j] = 0.f; }
            #pragma unroll
            for (int kk = 0; kk < 4; kk++) {
                mma_bf(S0a[p], qfh[kk], bh[kk][0], bh[kk][2]);
                mma_bf(S1a[p], qfh[kk], bh[kk][1], bh[kk][3]);
                mma_bf(S0a[p], qfh[kk], bl[kk][0], bl[kk][2]);
                mma_bf(S1a[p], qfh[kk], bl[kk][1], bl[kk][3]);
                mma_bf(S0a[p], qfl[kk], bh[kk][0], bh[kk][2]);
                mma_bf(S1a[p], qfl[kk], bh[kk][1], bh[kk][3]);
            }
        }

        // ---- tile-level online softmax ----
        float ca = -1e30f, cb = -1e30f;
        #pragma unroll
        for (int p = 0; p < 4; p++) {
            ca = fmaxf(ca, fmaxf(fmaxf(S0a[p][0], S0a[p][1]),
                                 fmaxf(S1a[p][0], S1a[p][1])));
            cb = fmaxf(cb, fmaxf(fmaxf(S0a[p][2], S0a[p][3]),
                                 fmaxf(S1a[p][2], S1a[p][3])));
        }
        ca = fmaxf(ca, __shfl_xor_sync(0xffffffffu, ca, 1));
        ca = fmaxf(ca, __shfl_xor_sync(0xffffffffu, ca, 2));
        cb = fmaxf(cb, __shfl_xor_sync(0xffffffffu, cb, 1));
        cb = fmaxf(cb, __shfl_xor_sync(0xffffffffu, cb, 2));
        float mna = fmaxf(ma, ca), mnb = fmaxf(mb, cb);
        float fa = mna * L2E, fb = mnb * L2E;
        float sa  = ex2a(ma * L2E - fa);
        float sbb = ex2a(mb * L2E - fb);
        ma = mna; mb = mnb;

        float suma = 0.f, sumb = 0.f;
        uint32_t Ah[4][4];
        #pragma unroll
        for (int p = 0; p < 4; p++) {
            float e00 = ex2a(fmaf(S0a[p][0], L2E, -fa));
            float e01 = ex2a(fmaf(S0a[p][1], L2E, -fa));
            float e02 = ex2a(fmaf(S0a[p][2], L2E, -fb));
            float e03 = ex2a(fmaf(S0a[p][3], L2E, -fb));
            float e10 = ex2a(fmaf(S1a[p][0], L2E, -fa));
            float e11 = ex2a(fmaf(S1a[p][1], L2E, -fa));
            float e12 = ex2a(fmaf(S1a[p][2], L2E, -fb));
            float e13 = ex2a(fmaf(S1a[p][3], L2E, -fb));
            suma += e00 + e01 + e10 + e11;
            sumb += e02 + e03 + e12 + e13;
            Ah[p][0] = h2u(__floats2half2_rn(e00, e01));
            Ah[p][1] = h2u(__floats2half2_rn(e02, e03));
            Ah[p][2] = h2u(__floats2half2_rn(e10, e11));
            Ah[p][3] = h2u(__floats2half2_rn(e12, e13));
        }
        la = la * sa  + suma;
        lb = lb * sbb + sumb;
        #pragma unroll
        for (int nb = 0; nb < 8; nb++) {
            O[nb][0] *= sa;  O[nb][1] *= sa;
            O[nb][2] *= sbb; O[nb][3] *= sbb;
        }

        // ---- MMA2: O += P Vh (fp16, single pass) ----
        #pragma unroll
        for (int p = 0; p < 4; p++) {
            uint32_t vb = vhB + (r15 << 7)
                        + ((((p * 2 + c16) ^ r7) & 7) << 4);
            #pragma unroll
            for (int np = 0; np < 4; np++) {
                uint32_t a = vb + (np << 11);
                uint32_t v0, v1, v2, v3;
                ldsm4(v0, v1, v2, v3, a);
                mma_fp(O[2 * np],     Ah[p], v0, v2);
                mma_fp(O[2 * np + 1], Ah[p], v1, v3);
            }
        }
    }

    // ---- epilogue: per-row l (quad reduce), normalize, coalesced store ----
    la += __shfl_xor_sync(0xffffffffu, la, 1);
    la += __shfl_xor_sync(0xffffffffu, la, 2);
    lb += __shfl_xor_sync(0xffffffffu, lb, 1);
    lb += __shfl_xor_sync(0xffffffffu, lb, 2);
    float ia = 1.0f / la, ib = 1.0f / lb;

    __syncthreads();
    float* o_s = (float*)smem;          // [64][132], overlays Q/KV smem
    #pragma unroll
    for (int nb = 0; nb < 8; nb++) {
        int c = nb * 8 + (lane & 3) * 2;
        int m = w * 16 + (lane >> 2);
        o_s[c * 132 + m]           = O[nb][0] * ia;
        o_s[(c + 1) * 132 + m]     = O[nb][1] * ia;
        o_s[c * 132 + m + 8]       = O[nb][2] * ib;
        o_s[(c + 1) * 132 + m + 8] = O[nb][3] * ib;
    }
    __syncthreads();
    for (int i = tid; i < 2048; i += 256) {
        int c = i >> 5, sg = i & 31;
        float4 v;
        v.x = o_s[c * 132 + sg * 4 + 0];
        v.y = o_s[c * 132 + sg * 4 + 1];
        v.z = o_s[c * 132 + sg * 4 + 2];
        v.w = o_s[c * 132 + sg * 4 + 3];
        *(float4*)(out + ((long)(b * CH + c)) * NN + n0 + sg * 4) = v;
    }
}

extern "C" void kernel_launch(void* const* d_in, const int* in_sizes, int n_in,
                              void* d_out, int out_size)
{
    const float* x     = (const float*)d_in[0];
    const float* Wq    = (const float*)d_in[1];
    const float* bq    = (const float*)d_in[2];
    const float* Wk    = (const float*)d_in[3];
    const float* bk    = (const float*)d_in[4];
    const float* Wv    = (const float*)d_in[5];
    const float* bv    = (const float*)d_in[6];
    const float* rel_h = (const float*)d_in[7];
    const float* rel_w = (const float*)d_in[8];
    float* out = (float*)d_out;

    cudaFuncSetAttribute(qkv_kernel, cudaFuncAttributeMaxDynamicSharedMemorySize,
                         QKV_SMEM);
    cudaFuncSetAttribute(attn_kernel, cudaFuncAttributeMaxDynamicSharedMemorySize,
                         ATT_SMEM);

    qkv_kernel<<<BB * 64, 256, QKV_SMEM>>>(x, Wq, bq, Wk, bk, Wv, bv, rel_h, rel_w);
    attn_kernel<<<BB * 32, 256, ATT_SMEM>>>(out);
}

// round 15
// speedup vs baseline: 1.7523x; 1.1452x over previous
#include <cuda_runtime.h>
#include <cuda_bf16.h>
#include <cuda_fp16.h>
#include <cstdint>

#define BB 4
#define CH 64
#define NN 4096

// ---------------- scratch (allocation-free) ----------------
__device__ __align__(16) __nv_bfloat16 g_qhi[BB * NN * CH];
__device__ __align__(16) __nv_bfloat16 g_qlo[BB * NN * CH];
__device__ __align__(16) __nv_bfloat16 g_khi[BB * NN * CH];
__device__ __align__(16) __nv_bfloat16 g_klo[BB * NN * CH];
__device__ __align__(16) __half        g_vh [BB * CH * NN];

// ---------------- helpers (base-target PTX only) ----------------
__device__ __forceinline__ uint32_t smem_u32(const void* p) {
    uint32_t a;
    asm("{ .reg .u64 t; cvta.to.shared.u64 t, %1; cvt.u32.u64 %0, t; }"
        : "=r"(a) : "l"(p));
    return a;
}
__device__ __forceinline__ void cp16(uint32_t dst, const void* src) {
    asm volatile("cp.async.cg.shared.global [%0], [%1], 16;"
                 :: "r"(dst), "l"(__cvta_generic_to_global(src)) : "memory");
}
__device__ __forceinline__ void cp_commit() {
    asm volatile("cp.async.commit_group;" ::: "memory");
}
__device__ __forceinline__ void cp_wait1() {
    asm volatile("cp.async.wait_group 1;" ::: "memory");
}
__device__ __forceinline__ void cp_wait0() {
    asm volatile("cp.async.wait_group 0;" ::: "memory");
}
__device__ __forceinline__ void ldsm4(uint32_t& r0, uint32_t& r1, uint32_t& r2,
                                      uint32_t& r3, uint32_t a) {
    asm volatile("ldmatrix.sync.aligned.m8n8.x4.shared.b16 {%0,%1,%2,%3}, [%4];"
                 : "=r"(r0), "=r"(r1), "=r"(r2), "=r"(r3) : "r"(a));
}
__device__ __forceinline__ void mma_bf(float* d, const uint32_t* a,
                                       uint32_t b0, uint32_t b1) {
    asm volatile("mma.sync.aligned.m16n8k16.row.col.f32.bf16.bf16.f32 "
                 "{%0,%1,%2,%3}, {%4,%5,%6,%7}, {%8,%9}, {%0,%1,%2,%3};"
                 : "+f"(d[0]), "+f"(d[1]), "+f"(d[2]), "+f"(d[3])
                 : "r"(a[0]), "r"(a[1]), "r"(a[2]), "r"(a[3]), "r"(b0), "r"(b1));
}
__device__ __forceinline__ void mma_fp(float* d, const uint32_t* a,
                                       uint32_t b0, uint32_t b1) {
    asm volatile("mma.sync.aligned.m16n8k16.row.col.f32.f16.f16.f32 "
                 "{%0,%1,%2,%3}, {%4,%5,%6,%7}, {%8,%9}, {%0,%1,%2,%3};"
                 : "+f"(d[0]), "+f"(d[1]), "+f"(d[2]), "+f"(d[3])
                 : "r"(a[0]), "r"(a[1]), "r"(a[2]), "r"(a[3]), "r"(b0), "r"(b1));
}
__device__ __forceinline__ uint32_t b2u(__nv_bfloat162 h) {
    return *reinterpret_cast<uint32_t*>(&h);
}
__device__ __forceinline__ uint32_t h2u(__half2 h) {
    return *reinterpret_cast<uint32_t*>(&h);
}
__device__ __forceinline__ float ex2a(float x) {
    float r;
    asm("ex2.approx.f32 %0, %1;" : "=f"(r) : "f"(x));
    return r;
}
#define L2E 1.44269504f

// ---------------------------------------------------------------------------
// Stage 1: projections. Q/K: bf16 hi/lo [B][N][C]; V: fp16 [B][C][N].
// ---------------------------------------------------------------------------
#define QKV_SMEM 69632

__global__ __launch_bounds__(256) void qkv_kernel(
    const float* __restrict__ x,
    const float* __restrict__ Wq, const float* __restrict__ bq,
    const float* __restrict__ Wk, const float* __restrict__ bk,
    const float* __restrict__ Wv, const float* __restrict__ bv,
    const float* __restrict__ rel_h, const float* __restrict__ rel_w)
{
    extern __shared__ float sm1[];
    float* w_s = sm1;              // [3][64 c][68]
    float* xs  = sm1 + 13056;      // [64 c][68]
    float* res = xs;               // alias

    int b  = blockIdx.x >> 6;
    int n0 = (blockIdx.x & 63) << 6;
    int t  = threadIdx.x;

    for (int i = t; i < 4096; i += 256) {
        int o = i >> 6, c = i & 63;
        w_s[c * 68 + o]        = Wq[i];
        w_s[4352 + c * 68 + o] = Wk[i];
        w_s[8704 + c * 68 + o] = Wv[i];
        xs[o * 68 + c]         = x[((long)b * CH + o) * NN + n0 + c];
    }
    __syncthreads();

    int og = (t & 15) << 2;
    int ng = (t >> 4) << 2;

    float aq[4][4] = {}, ak[4][4] = {}, av[4][4] = {};
    #pragma unroll 4
    for (int c = 0; c < 64; c++) {
        float4 xv4 = *(const float4*)&xs[c * 68 + ng];
        float4 wq4 = *(const float4*)&w_s[c * 68 + og];
        float4 wk4 = *(const float4*)&w_s[4352 + c * 68 + og];
        float4 wv4 = *(const float4*)&w_s[8704 + c * 68 + og];
        float xv[4] = {xv4.x, xv4.y, xv4.z, xv4.w};
        float wq[4] = {wq4.x, wq4.y, wq4.z, wq4.w};
        float wk[4] = {wk4.x, wk4.y, wk4.z, wk4.w};
        float wv[4] = {wv4.x, wv4.y, wv4.z, wv4.w};
        #pragma unroll
        for (int i = 0; i < 4; i++)
            #pragma unroll
            for (int j = 0; j < 4; j++) {
                aq[i][j] = fmaf(wq[i], xv[j], aq[i][j]);
                ak[i][j] = fmaf(wk[i], xv[j], ak[i][j]);
                av[i][j] = fmaf(wv[i], xv[j], av[i][j]);
            }
    }

    long nbase = ((long)b * NN + n0) * CH;
    float bq0 = __ldg(&bq[og]), bq1 = __ldg(&bq[og + 1]),
          bq2 = __ldg(&bq[og + 2]), bq3 = __ldg(&bq[og + 3]);
    float bk0 = __ldg(&bk[og]), bk1 = __ldg(&bk[og + 1]),
          bk2 = __ldg(&bk[og + 2]), bk3 = __ldg(&bk[og + 3]);

    #pragma unroll
    for (int j = 0; j < 4; j++) {
        int gn = n0 + ng + j, hh = gn >> 6, ww = gn & 63;
        long row = nbase + (long)(ng + j) * CH + og;
        {
            float v0 = aq[0][j] + bq0, v1 = aq[1][j] + bq1;
            float v2 = aq[2][j] + bq2, v3 = aq[3][j] + bq3;
            __nv_bfloat162 h01 = __floats2bfloat162_rn(v0, v1);
            __nv_bfloat162 h23 = __floats2bfloat162_rn(v2, v3);
            __nv_bfloat162 l01 = __floats2bfloat162_rn(v0 - __bfloat162float(h01.x),
                                                       v1 - __bfloat162float(h01.y));
            __nv_bfloat162 l23 = __floats2bfloat162_rn(v2 - __bfloat162float(h23.x),
                                                       v3 - __bfloat162float(h23.y));
            *(uint2*)&g_qhi[row] = make_uint2(b2u(h01), b2u(h23));
            *(uint2*)&g_qlo[row] = make_uint2(b2u(l01), b2u(l23));
        }
        {
            float v0 = ak[0][j] + bk0 + __ldg(&rel_h[og * 64 + hh])       + __ldg(&rel_w[og * 64 + ww]);
            float v1 = ak[1][j] + bk1 + __ldg(&rel_h[(og + 1) * 64 + hh]) + __ldg(&rel_w[(og + 1) * 64 + ww]);
            float v2 = ak[2][j] + bk2 + __ldg(&rel_h[(og + 2) * 64 + hh]) + __ldg(&rel_w[(og + 2) * 64 + ww]);
            float v3 = ak[3][j] + bk3 + __ldg(&rel_h[(og + 3) * 64 + hh]) + __ldg(&rel_w[(og + 3) * 64 + ww]);
            __nv_bfloat162 h01 = __floats2bfloat162_rn(v0, v1);
            __nv_bfloat162 h23 = __floats2bfloat162_rn(v2, v3);
            __nv_bfloat162 l01 = __floats2bfloat162_rn(v0 - __bfloat162float(h01.x),
                                                       v1 - __bfloat162float(h01.y));
            __nv_bfloat162 l23 = __floats2bfloat162_rn(v2 - __bfloat162float(h23.x),
                                                       v3 - __bfloat162float(h23.y));
            *(uint2*)&g_khi[row] = make_uint2(b2u(h01), b2u(h23));
            *(uint2*)&g_klo[row] = make_uint2(b2u(l01), b2u(l23));
        }
    }

    __syncthreads();
    float bv0 = __ldg(&bv[og]), bv1 = __ldg(&bv[og + 1]),
          bv2 = __ldg(&bv[og + 2]), bv3 = __ldg(&bv[og + 3]);
    #pragma unroll
    for (int j = 0; j < 4; j++) {
        res[(og + 0) * 65 + ng + j] = av[0][j] + bv0;
        res[(og + 1) * 65 + ng + j] = av[1][j] + bv1;
        res[(og + 2) * 65 + ng + j] = av[2][j] + bv2;
        res[(og + 3) * 65 + ng + j] = av[3][j] + bv3;
    }
    __syncthreads();
    for (int i = t; i < 2048; i += 256) {
        int e = i * 2, c = e >> 6, n = e & 63;
        __half2 h = __floats2half2_rn(res[c * 65 + n], res[c * 65 + n + 1]);
        *(__half2*)&g_vh[((long)b * CH + c) * NN + n0 + n] = h;
    }
}

// ---------------------------------------------------------------------------
// Stage 2: FA2, tile-level online softmax, SOFTWARE-PIPELINED tiles:
// softmax(it) overlaps MMA1(it+1) via S register bank ping-pong; 3 KV smem
// buffers (prefetch distance 2). QK bf16 3-pass; PV fp16 1-pass.
// smem: QHI 16K | QLO 16K | buf0..2 24K each (KHI 8K|KLO 8K|V 8K)
// ---------------------------------------------------------------------------
#define SM_KV    32768
#define KV_BYTES 24576
#define ATT_SMEM (32768 + 3 * 24576)   // 106496

__device__ __forceinline__ void load_kv(uint32_t base, int b, int m0, int tid) {
    const __nv_bfloat16* kh = g_khi + ((long)b * NN + m0) * CH;
    const __nv_bfloat16* kl = g_klo + ((long)b * NN + m0) * CH;
    #pragma unroll
    for (int j = 0; j < 2; j++) {
        int i = tid + j * 256;
        int m = i >> 3, ch = i & 7;
        uint32_t d = base + (m << 7) + (((ch ^ (m & 7)) & 7) << 4);
        cp16(d, kh + m * 64 + ch * 8);
        cp16(d + 8192, kl + m * 64 + ch * 8);
    }
    const __half* vh = g_vh + (long)b * CH * NN + m0;
    #pragma unroll
    for (int j = 0; j < 2; j++) {
        int i = tid + j * 256;
        int c = i >> 3, ch = i & 7;
        uint32_t d = base + 16384 + (c << 7) + (((ch ^ (c & 7)) & 7) << 4);
        cp16(d, vh + (long)c * NN + ch * 8);
    }
}

// MMA1: compute S for a 64-key tile from K buffer KB into (D0, D1)
#define MMA1_TILE(D0, D1, KB)                                                  \
    {                                                                          \
        _Pragma("unroll")                                                      \
        for (int p = 0; p < 4; p++) {                                          \
            uint32_t bh[4][4], bl[4][4];                                       \
            _Pragma("unroll")                                                  \
            for (int kk = 0; kk < 4; kk++) {                                   \
                uint32_t a = (KB) + ksw[kk] + (p << 11);                       \
                ldsm4(bh[kk][0], bh[kk][1], bh[kk][2], bh[kk][3], a);          \
                ldsm4(bl[kk][0], bl[kk][1], bl[kk][2], bl[kk][3], a + 8192);   \
            }                                                                  \
            _Pragma("unroll")                                                  \
            for (int j = 0; j < 4; j++) { D0[p][j] = 0.f; D1[p][j] = 0.f; }    \
            _Pragma("unroll")                                                  \
            for (int kk = 0; kk < 4; kk++) {                                   \
                mma_bf(D0[p], qfh[kk], bh[kk][0], bh[kk][2]);                  \
                mma_bf(D1[p], qfh[kk], bh[kk][1], bh[kk][3]);                  \
                mma_bf(D0[p], qfh[kk], bl[kk][0], bl[kk][2]);                  \
                mma_bf(D1[p], qfh[kk], bl[kk][1], bl[kk][3]);                  \
                mma_bf(D0[p], qfl[kk], bh[kk][0], bh[kk][2]);                  \
                mma_bf(D1[p], qfl[kk], bh[kk][1], bh[kk][3]);                  \
            }                                                                  \
        }                                                                      \
    }

// softmax on (C0, C1) -> Ah + l/m/O update
#define SOFTMAX_TILE(C0, C1)                                                   \
    {                                                                          \
        float ca = -1e30f, cb = -1e30f;                                        \
        _Pragma("unroll")                                                      \
        for (int p = 0; p < 4; p++) {                                          \
            ca = fmaxf(ca, fmaxf(fmaxf(C0[p][0], C0[p][1]),                    \
                                 fmaxf(C1[p][0], C1[p][1])));                  \
            cb = fmaxf(cb, fmaxf(fmaxf(C0[p][2], C0[p][3]),                    \
                                 fmaxf(C1[p][2], C1[p][3])));                  \
        }                                                                      \
        ca = fmaxf(ca, __shfl_xor_sync(0xffffffffu, ca, 1));                   \
        ca = fmaxf(ca, __shfl_xor_sync(0xffffffffu, ca, 2));                   \
        cb = fmaxf(cb, __shfl_xor_sync(0xffffffffu, cb, 1));                   \
        cb = fmaxf(cb, __shfl_xor_sync(0xffffffffu, cb, 2));                   \
        float mna = fmaxf(ma, ca), mnb = fmaxf(mb, cb);                        \
        float fa = mna * L2E, fb = mnb * L2E;                                  \
        float sa  = ex2a(ma * L2E - fa);                                       \
        float sbb = ex2a(mb * L2E - fb);                                       \
        ma = mna; mb = mnb;                                                    \
        float suma = 0.f, sumb = 0.f;                                          \
        _Pragma("unroll")                                                      \
        for (int p = 0; p < 4; p++) {                                          \
            float e00 = ex2a(fmaf(C0[p][0], L2E, -fa));                        \
            float e01 = ex2a(fmaf(C0[p][1], L2E, -fa));                        \
            float e02 = ex2a(fmaf(C0[p][2], L2E, -fb));                        \
            float e03 = ex2a(fmaf(C0[p][3], L2E, -fb));                        \
            float e10 = ex2a(fmaf(C1[p][0], L2E, -fa));                        \
            float e11 = ex2a(fmaf(C1[p][1], L2E, -fa));                        \
            float e12 = ex2a(fmaf(C1[p][2], L2E, -fb));                        \
            float e13 = ex2a(fmaf(C1[p][3], L2E, -fb));                        \
            suma += e00 + e01 + e10 + e11;                                     \
            sumb += e02 + e03 + e12 + e13;                                     \
            Ah[p][0] = h2u(__floats2half2_rn(e00, e01));                       \
            Ah[p][1] = h2u(__floats2half2_rn(e02, e03));                       \
            Ah[p][2] = h2u(__floats2half2_rn(e10, e11));                       \
            Ah[p][3] = h2u(__floats2half2_rn(e12, e13));                       \
        }                                                                      \
        la = la * sa  + suma;                                                  \
        lb = lb * sbb + sumb;                                                  \
        _Pragma("unroll")                                                      \
        for (int nb = 0; nb < 8; nb++) {                                       \
            O[nb][0] *= sa;  O[nb][1] *= sa;                                   \
            O[nb][2] *= sbb; O[nb][3] *= sbb;                                  \
        }                                                                      \
    }

// MMA2: O += P(Ah) * V from buffer VB
#define MMA2_TILE(VB)                                                          \
    {                                                                          \
        _Pragma("unroll")                                                      \
        for (int p = 0; p < 4; p++) {                                          \
            uint32_t vb = (VB) + 16384 + (r15 << 7)                            \
                        + ((((p * 2 + c16) ^ r7) & 7) << 4);                   \
            _Pragma("unroll")                                                  \
            for (int np = 0; np < 4; np++) {                                   \
                uint32_t a = vb + (np << 11);                                  \
                uint32_t v0, v1, v2, v3;                                       \
                ldsm4(v0, v1, v2, v3, a);                                      \
                mma_fp(O[2 * np],     Ah[p], v0, v2);                          \
                mma_fp(O[2 * np + 1], Ah[p], v1, v3);                          \
            }                                                                  \
        }                                                                      \
    }

__global__ __launch_bounds__(256, 1) void attn_kernel(float* __restrict__ out)
{
    extern __shared__ char smem[];
    uint32_t sb = smem_u32(smem);
    int tid = threadIdx.x;
    int w = tid >> 5, lane = tid & 31;
    int b  = blockIdx.x >> 5;
    int n0 = (blockIdx.x & 31) << 7;

    // ---- prologue: Q group, kv0 group, kv1 group ----
    {
        const __nv_bfloat16* qh = g_qhi + ((long)b * NN + n0) * CH;
        const __nv_bfloat16* ql = g_qlo + ((long)b * NN + n0) * CH;
        #pragma unroll
        for (int j = 0; j < 4; j++) {
            int i = tid + j * 256;
            int m = i >> 3, ch = i & 7;
            uint32_t d = sb + (m << 7) + (((ch ^ (m & 7)) & 7) << 4);
            cp16(d, qh + m * 64 + ch * 8);
            cp16(d + 16384, ql + m * 64 + ch * 8);
        }
        cp_commit();
    }
    load_kv(sb + SM_KV, b, 0, tid);
    cp_commit();
    load_kv(sb + SM_KV + KV_BYTES, b, 64, tid);
    cp_commit();
    cp_wait1();           // Q + kv0 done; kv1 in flight
    __syncthreads();

    int r15 = lane & 15, c16 = lane >> 4;
    int r7 = r15 & 7;

    // ---- Q fragments, register-resident for the whole loop ----
    uint32_t qfh[4][4], qfl[4][4];
    #pragma unroll
    for (int kk = 0; kk < 4; kk++) {
        int r = w * 16 + r15;
        int cc = kk * 2 + c16;
        uint32_t a = sb + (r << 7) + (((cc ^ (r & 7)) & 7) << 4);
        ldsm4(qfh[kk][0], qfh[kk][1], qfh[kk][2], qfh[kk][3], a);
        ldsm4(qfl[kk][0], qfl[kk][1], qfl[kk][2], qfl[kk][3], a + 16384);
    }

    uint32_t ksw[4];
    #pragma unroll
    for (int kk = 0; kk < 4; kk++)
        ksw[kk] = (r15 << 7) + ((((kk * 2 + c16) ^ r7) & 7) << 4);

    float O[8][4];
    #pragma unroll
    for (int i = 0; i < 8; i++)
        #pragma unroll
        for (int j = 0; j < 4; j++) O[i][j] = 0.f;
    float la = 0.f, lb = 0.f;
    float ma = -1e30f, mb = -1e30f;

    // S register banks (ping-pong) + P fragments
    float SA0[4][4], SA1[4][4], SB0[4][4], SB1[4][4];
    uint32_t Ah[4][4];

    uint32_t bufA = sb + SM_KV;                 // kv(it)
    uint32_t bufB = sb + SM_KV + KV_BYTES;      // kv(it+1)
    uint32_t bufC = sb + SM_KV + 2 * KV_BYTES;  // free / loading kv(it+2)

    // MMA1(0) into bank A (kv0 ready)
    MMA1_TILE(SA0, SA1, bufA);

    // main loop: bodies it = 0..62 (MMA1 of it+1 pipelined); peel it = 63
    #pragma unroll 2
    for (int it = 0; it < 63; it++) {
        cp_wait0();            // kv(it+1) landed
        __syncthreads();       // all warps done reading old bufC contents
        if (it + 2 < 64) {
            load_kv(bufC, b, (it + 2) << 6, tid);
            cp_commit();
        }
        if ((it & 1) == 0) {
            SOFTMAX_TILE(SA0, SA1);          // consume bank A
            MMA1_TILE(SB0, SB1, bufB);       // produce bank B (overlaps softmax)
        } else {
            SOFTMAX_TILE(SB0, SB1);
            MMA1_TILE(SA0, SA1, bufB);
        }
        MMA2_TILE(bufA);
        uint32_t tmp = bufA; bufA = bufB; bufB = bufC; bufC = tmp;
    }
    // peel it = 63: S(63) is in bank B (63&1==1), V(63) in bufA
    {
        SOFTMAX_TILE(SB0, SB1);
        MMA2_TILE(bufA);
    }

    // ---- epilogue: per-row l (quad reduce), normalize, coalesced store ----
    la += __shfl_xor_sync(0xffffffffu, la, 1);
    la += __shfl_xor_sync(0xffffffffu, la, 2);
    lb += __shfl_xor_sync(0xffffffffu, lb, 1);
    lb += __shfl_xor_sync(0xffffffffu, lb, 2);
    float ia = 1.0f / la, ib = 1.0f / lb;

    __syncthreads();
    float* o_s = (float*)smem;          // [64][132], overlays Q/KV smem
    #pragma unroll
    for (int nb = 0; nb < 8; nb++) {
        int c = nb * 8 + (lane & 3) * 2;
        int m = w * 16 + (lane >> 2);
        o_s[c * 132 + m]           = O[nb][0] * ia;
        o_s[(c + 1) * 132 + m]     = O[nb][1] * ia;
        o_s[c * 132 + m + 8]       = O[nb][2] * ib;
        o_s[(c + 1) * 132 + m + 8] = O[nb][3] * ib;
    }
    __syncthreads();
    for (int i = tid; i < 2048; i += 256) {
        int c = i >> 5, sg = i & 31;
        float4 v;
        v.x = o_s[c * 132 + sg * 4 + 0];
        v.y = o_s[c * 132 + sg * 4 + 1];
        v.z = o_s[c * 132 + sg * 4 + 2];
        v.w = o_s[c * 132 + sg * 4 + 3];
        *(float4*)(out + ((long)(b * CH + c)) * NN + n0 + sg * 4) = v;
    }
}

extern "C" void kernel_launch(void* const* d_in, const int* in_sizes, int n_in,
                              void* d_out, int out_size)
{
    const float* x     = (const float*)d_in[0];
    const float* Wq    = (const float*)d_in[1];
    const float* bq    = (const float*)d_in[2];
    const float* Wk    = (const float*)d_in[3];
    const float* bk    = (const float*)d_in[4];
    const float* Wv    = (const float*)d_in[5];
    const float* bv    = (const float*)d_in[6];
    const float* rel_h = (const float*)d_in[7];
    const float* rel_w = (const float*)d_in[8];
    float* out = (float*)d_out;

    cudaFuncSetAttribute(qkv_kernel, cudaFuncAttributeMaxDynamicSharedMemorySize,
                         QKV_SMEM);
    cudaFuncSetAttribute(attn_kernel, cudaFuncAttributeMaxDynamicSharedMemorySize,
                         ATT_SMEM);

    qkv_kernel<<<BB * 64, 256, QKV_SMEM>>>(x, Wq, bq, Wk, bk, Wv, bv, rel_h, rel_w);
    attn_kernel<<<BB * 32, 256, ATT_SMEM>>>(out);
}